// round 6
// baseline (speedup 1.0000x reference)
#include <cuda_runtime.h>
#include <stdint.h>

#define CN 128      // channels
#define NGR 128     // num graphs
#define BT 64       // rows per GEMM block tile
#define AP 132      // padded smem pitch (floats) for A tile (>= CN, float4-aligned)
#define CP 132      // pitch for C tile (float4-aligned)
#define SROWS 512   // rows per stats block
#define EPSV 1e-5f

// ---- small device-global scratch (statistics only; big buffers live in d_out) ----
__device__ float g_sum1[NGR*CN];
__device__ float g_sq1 [NGR*CN];
__device__ float g_sum2[NGR*CN];
__device__ float g_sq2 [NGR*CN];
__device__ float g_scale1[NGR*CN];
__device__ float g_shift1[NGR*CN];
__device__ float g_scale2[NGR*CN];
__device__ float g_shift2[NGR*CN];
__device__ int   g_cnt1[NGR];
__device__ int   g_cnt2[NGR];

// ---- Blackwell packed-fp32 helpers ----
__device__ __forceinline__ unsigned long long pack2(float a) {
    unsigned int u = __float_as_uint(a);
    unsigned long long r;
    asm("mov.b64 %0, {%1, %1};" : "=l"(r) : "r"(u));
    return r;
}
__device__ __forceinline__ void fma2(unsigned long long& d, unsigned long long a, unsigned long long b) {
    asm("fma.rn.f32x2 %0, %1, %2, %0;" : "+l"(d) : "l"(a), "l"(b));
}
__device__ __forceinline__ void red4(float* p, float x, float y, float z, float w) {
    asm volatile("red.global.add.v4.f32 [%0], {%1,%2,%3,%4};"
                 :: "l"(p), "f"(x), "f"(y), "f"(z), "f"(w) : "memory");
}

// ---- zero the small stats buffers ----
__global__ void zero_stats_kernel() {
    int i = blockIdx.x * blockDim.x + threadIdx.x;
    if (i < NGR*CN) { g_sum1[i]=0.f; g_sq1[i]=0.f; g_sum2[i]=0.f; g_sq2[i]=0.f; }
    if (i < NGR)    { g_cnt1[i]=0;   g_cnt2[i]=0; }
}

// ---- per-graph element counts (batch histogram) ----
__global__ void count_kernel(const int* __restrict__ b, int n, int which) {
    __shared__ int s[NGR];
    int* cnt = which ? g_cnt2 : g_cnt1;
    for (int i = threadIdx.x; i < NGR; i += blockDim.x) s[i] = 0;
    __syncthreads();
    for (long i = (long)blockIdx.x*blockDim.x + threadIdx.x; i < n; i += (long)gridDim.x*blockDim.x)
        atomicAdd(&s[b[i]], 1);
    __syncthreads();
    for (int i = threadIdx.x; i < NGR; i += blockDim.x) if (s[i]) atomicAdd(&cnt[i], s[i]);
}

// ---- fused: C_tile = A_tile @ W; 256 threads, per-thread 4 rows x 8 cols (f32x2).
//      If NORM: apply GraphNorm-1 affine to A rows and write them back as x_1_out.
//      Else:    pass A tile through to wb (x_2 output copy).
//      Then scatter-add DEG entries per source row into agg (v4 global red).
//      cols are structured: col(e) = e / DEG, so no cols array needed. ----
template<int DEG, bool NORM>
__global__ __launch_bounds__(256, 2) void fused_gemm_scatter(
    const float* __restrict__ A, const float* __restrict__ W,
    const int* __restrict__ rows, const float* __restrict__ vals,
    float* __restrict__ agg,
    const int* __restrict__ batch, float* __restrict__ wb, int n)
{
    extern __shared__ float smem[];
    float* Ws = smem;                         // CN*CN floats (reused as C tile later)
    float* As = smem + CN*CN;                 // BT*AP floats
    int*   s_rows = (int*)(As + BT*AP);       // BT*DEG
    float* s_vals = (float*)(s_rows + BT*DEG);

    const int tid  = threadIdx.x;
    const int j0   = blockIdx.x * BT;
    const int nrow = min(BT, n - j0);

    // load W (row-major [k][c]) into smem
    {
        const float4* W4 = (const float4*)W;
        float4* Ws4 = (float4*)Ws;
        for (int i = tid; i < CN*CN/4; i += 256) Ws4[i] = W4[i];
    }
    // load A tile; NORM: normalize + write back as output; else pass-through copy
    {
        const float4* A4 = (const float4*)A;
        for (int i = tid; i < BT*32; i += 256) {
            int r = i >> 5, cq = i & 31;
            float4 v = make_float4(0.f, 0.f, 0.f, 0.f);
            if (r < nrow) {
                long idx = (long)(j0 + r) * 32 + cq;
                v = A4[idx];
                if (NORM) {
                    int g = batch[j0 + r];
                    float4 a = ((const float4*)g_scale1)[g*32 + cq];
                    float4 b = ((const float4*)g_shift1)[g*32 + cq];
                    v.x = v.x*a.x + b.x; v.y = v.y*a.y + b.y;
                    v.z = v.z*a.z + b.z; v.w = v.w*a.w + b.w;
                }
                ((float4*)wb)[idx] = v;
            }
            *(float4*)&As[r*AP + cq*4] = v;
        }
    }
    // stage scatter metadata (rows + vals; cols are implicit)
    for (int i = tid; i < nrow*DEG; i += 256) {
        long e = (long)j0*DEG + i;
        s_rows[i] = rows[e];
        s_vals[i] = vals[e];
    }
    __syncthreads();

    // GEMM: thread computes rows r0..r0+3, cols c0..c0+7 (4 f32x2 per row)
    const int c0 = (tid & 15) << 3;
    const int r0 = (tid >> 4) << 2;
    unsigned long long acc[16];
#pragma unroll
    for (int i = 0; i < 16; i++) acc[i] = 0ULL;

    const float* A0 = &As[r0*AP];
#pragma unroll 1
    for (int k4 = 0; k4 < CN; k4 += 4) {
        float4 av[4];
#pragma unroll
        for (int i = 0; i < 4; i++) av[i] = *(const float4*)&A0[i*AP + k4];
#pragma unroll
        for (int kk = 0; kk < 4; kk++) {
            union { float4 f; unsigned long long u[2]; } w0, w1;
            w0.f = *(const float4*)&Ws[(k4+kk)*CN + c0];
            w1.f = *(const float4*)&Ws[(k4+kk)*CN + c0 + 4];
#pragma unroll
            for (int i = 0; i < 4; i++) {
                float as = (kk == 0) ? av[i].x : (kk == 1) ? av[i].y : (kk == 2) ? av[i].z : av[i].w;
                unsigned long long a = pack2(as);
                fma2(acc[i*4+0], a, w0.u[0]);
                fma2(acc[i*4+1], a, w0.u[1]);
                fma2(acc[i*4+2], a, w1.u[0]);
                fma2(acc[i*4+3], a, w1.u[1]);
            }
        }
    }
    __syncthreads();   // all warps done reading W -> reuse region as C tile

    float* Cs = Ws;    // BT x CP
#pragma unroll
    for (int i = 0; i < 4; i++) {
        float2* dst = (float2*)&Cs[(r0+i)*CP + c0];
#pragma unroll
        for (int j = 0; j < 4; j++) {
            union { unsigned long long u; float2 f; } t;
            t.u = acc[i*4+j];
            dst[j] = t.f;
        }
    }
    __syncthreads();

    // scatter: one v4 reduction per (entry, 4-channel group); src col = e/DEG
    const int total = nrow * DEG * 32;
    for (int idx = tid; idx < total; idx += 256) {
        int e = idx >> 5, q = idx & 31;
        int src = e / DEG;
        float v = s_vals[e];
        float4 y = *(const float4*)&Cs[src*CP + q*4];
        float* p = agg + (long)s_rows[e]*CN + q*4;
        red4(p, v*y.x, v*y.y, v*y.z, v*y.w);
    }
}

// ---- per-(graph,channel) sum and sumsq with block-local segmented runs (batch sorted) ----
__global__ void stats_kernel(const float* __restrict__ y, const int* __restrict__ batch,
                             int n, int which)
{
    float* sum = which ? g_sum2 : g_sum1;
    float* sq  = which ? g_sq2  : g_sq1;
    int c  = threadIdx.x & (CN-1);
    int p  = threadIdx.x >> 7;
    int r0 = blockIdx.x * SROWS;
    int rend = min(r0 + SROWS, n);
    float rs = 0.f, rq = 0.f;
    int cur = -1;
    for (int r = r0 + p; r < rend; r += 2) {
        int g = batch[r];
        if (g != cur) {
            if (cur >= 0) { atomicAdd(&sum[cur*CN+c], rs); atomicAdd(&sq[cur*CN+c], rq); }
            cur = g; rs = 0.f; rq = 0.f;
        }
        float v = y[(long)r*CN + c];
        rs += v; rq += v*v;
    }
    if (cur >= 0) { atomicAdd(&sum[cur*CN+c], rs); atomicAdd(&sq[cur*CN+c], rq); }
}

// ---- turn sums into per-(graph,channel) affine scale/shift ----
__global__ void finalize_kernel(const float* __restrict__ wgt, const float* __restrict__ bias,
                                const float* __restrict__ mscale, int which)
{
    int i = blockIdx.x*blockDim.x + threadIdx.x;
    if (i >= NGR*CN) return;
    const float* sum = which ? g_sum2 : g_sum1;
    const float* sq  = which ? g_sq2  : g_sq1;
    const int*   cnt = which ? g_cnt2 : g_cnt1;
    float* sc = which ? g_scale2 : g_scale1;
    float* sh = which ? g_shift2 : g_shift1;
    int g = i >> 7, c = i & (CN-1);
    float nf  = fmaxf((float)cnt[g], 1.f);
    float m   = sum[i] / nf;
    float ms  = m * mscale[c];
    float var = sq[i]/nf - 2.f*ms*m + ms*ms;   // E[(x - m*s)^2]
    float inv = rsqrtf(var + EPSV);
    float a   = wgt[c] * inv;
    sc[i] = a;
    sh[i] = bias[c] - ms * a;
}

// ---- final normalization of x_0_out (GraphNorm-2 application) ----
__global__ void apply_norm_kernel(float* __restrict__ y, const int* __restrict__ batch, int n)
{
    long idx = (long)blockIdx.x*blockDim.x + threadIdx.x;   // one float4
    if (idx >= (long)n*32) return;
    int r = (int)(idx >> 5); int cq = (int)(idx & 31);
    int g = batch[r];
    float4 v = ((float4*)y)[idx];
    float4 a = ((const float4*)g_scale2)[g*32+cq];
    float4 b = ((const float4*)g_shift2)[g*32+cq];
    v.x = v.x*a.x + b.x; v.y = v.y*a.y + b.y;
    v.z = v.z*a.z + b.z; v.w = v.w*a.w + b.w;
    ((float4*)y)[idx] = v;
}

extern "C" void kernel_launch(void* const* d_in, const int* in_sizes, int n_in,
                              void* d_out, int out_size)
{
    const float* x0   = (const float*)d_in[0];
    const float* x1   = (const float*)d_in[1];
    const float* x2   = (const float*)d_in[2];
    const float* W1   = (const float*)d_in[3];
    const float* W2   = (const float*)d_in[4];
    const float* gn1w = (const float*)d_in[5];
    const float* gn1b = (const float*)d_in[6];
    const float* gn1m = (const float*)d_in[7];
    const float* gn2w = (const float*)d_in[8];
    const float* gn2b = (const float*)d_in[9];
    const float* gn2m = (const float*)d_in[10];
    const int*   i2r  = (const int*)d_in[11];
    // d_in[12] = inc2_cols (structured, unused)
    const float* i2v  = (const float*)d_in[13];
    const int*   i1r  = (const int*)d_in[14];
    // d_in[15] = inc1_cols (structured, unused)
    const float* i1v  = (const float*)d_in[16];
    const int*   bn   = (const int*)d_in[17];
    const int*   be   = (const int*)d_in[18];

    const int n0 = in_sizes[0] / CN;
    const int n1 = in_sizes[1] / CN;
    const int n2 = in_sizes[2] / CN;

    float* out_x0 = (float*)d_out;
    float* out_x1 = out_x0 + (size_t)n0 * CN;
    float* out_x2 = out_x1 + (size_t)n1 * CN;

    const size_t SM3 = (size_t)(CN*CN + BT*AP)*4 + (size_t)BT*3*8;
    const size_t SM2 = (size_t)(CN*CN + BT*AP)*4 + (size_t)BT*2*8;
    cudaFuncSetAttribute((const void*)fused_gemm_scatter<3,false>,
                         cudaFuncAttributeMaxDynamicSharedMemorySize, (int)SM3);
    cudaFuncSetAttribute((const void*)fused_gemm_scatter<2,true>,
                         cudaFuncAttributeMaxDynamicSharedMemorySize, (int)SM2);

    // residual pre-fill of outputs (x_2 copy is fused into GEMM1's A-load)
    cudaMemcpyAsync(out_x0, x0, (size_t)n0*CN*sizeof(float), cudaMemcpyDeviceToDevice, 0);
    cudaMemcpyAsync(out_x1, x1, (size_t)n1*CN*sizeof(float), cudaMemcpyDeviceToDevice, 0);

    zero_stats_kernel<<<64, 256>>>();
    count_kernel<<<232, 256>>>(be, n1, 0);
    count_kernel<<<232, 256>>>(bn, n0, 1);

    // layer 1: out_x1 += inc2 @ (x_2 @ W1); out_x2 = x_2 (fused copy)
    fused_gemm_scatter<3,false><<<(n2+BT-1)/BT, 256, SM3>>>(
        x2, W1, i2r, i2v, out_x1, nullptr, out_x2, n2);
    stats_kernel<<<(n1+SROWS-1)/SROWS, 256>>>(out_x1, be, n1, 0);
    finalize_kernel<<<64, 256>>>(gn1w, gn1b, gn1m, 0);

    // layer 2: normalize x_1_out in-flight, out_x0 += inc1 @ (x_1_out @ W2)
    fused_gemm_scatter<2,true><<<(n1+BT-1)/BT, 256, SM2>>>(
        out_x1, W2, i1r, i1v, out_x0, be, out_x1, n1);
    stats_kernel<<<(n0+SROWS-1)/SROWS, 256>>>(out_x0, bn, n0, 1);
    finalize_kernel<<<64, 256>>>(gn2w, gn2b, gn2m, 1);
    apply_norm_kernel<<<(int)(((long)n0*32 + 255)/256), 256>>>(out_x0, bn, n0);
}

// round 10
// speedup vs baseline: 1.1714x; 1.1714x over previous
#include <cuda_runtime.h>
#include <stdint.h>

#define CN 128      // channels
#define NGR 128     // num graphs
#define BT 64       // rows per GEMM block tile
#define AP 132      // padded smem pitch (floats) for A tile (>= CN, float4-aligned)
#define CP 132      // pitch for C tile (float4-aligned)
#define SROWS 512   // rows per stats block
#define EPSV 1e-5f

// ---- small device-global scratch (statistics only; big buffers live in d_out) ----
__device__ float g_sum1[NGR*CN];
__device__ float g_sq1 [NGR*CN];
__device__ float g_sum2[NGR*CN];
__device__ float g_sq2 [NGR*CN];
__device__ float g_scale1[NGR*CN];
__device__ float g_shift1[NGR*CN];
__device__ float g_scale2[NGR*CN];
__device__ float g_shift2[NGR*CN];
__device__ int   g_cnt1[NGR];
__device__ int   g_cnt2[NGR];

// ---- Blackwell packed-fp32 helpers ----
__device__ __forceinline__ unsigned long long pack2(float a) {
    unsigned int u = __float_as_uint(a);
    unsigned long long r;
    asm("mov.b64 %0, {%1, %1};" : "=l"(r) : "r"(u));
    return r;
}
__device__ __forceinline__ void fma2(unsigned long long& d, unsigned long long a, unsigned long long b) {
    asm("fma.rn.f32x2 %0, %1, %2, %0;" : "+l"(d) : "l"(a), "l"(b));
}
__device__ __forceinline__ void red4(float* p, float x, float y, float z, float w) {
    asm volatile("red.global.add.v4.f32 [%0], {%1,%2,%3,%4};"
                 :: "l"(p), "f"(x), "f"(y), "f"(z), "f"(w) : "memory");
}

// ---- zero the small stats buffers ----
__global__ void zero_stats_kernel() {
    int i = blockIdx.x * blockDim.x + threadIdx.x;
    if (i < NGR*CN) { g_sum1[i]=0.f; g_sq1[i]=0.f; g_sum2[i]=0.f; g_sq2[i]=0.f; }
    if (i < NGR)    { g_cnt1[i]=0;   g_cnt2[i]=0; }
}

// ---- per-graph element counts (batch histogram) ----
__global__ void count_kernel(const int* __restrict__ b, int n, int which) {
    __shared__ int s[NGR];
    int* cnt = which ? g_cnt2 : g_cnt1;
    for (int i = threadIdx.x; i < NGR; i += blockDim.x) s[i] = 0;
    __syncthreads();
    for (long i = (long)blockIdx.x*blockDim.x + threadIdx.x; i < n; i += (long)gridDim.x*blockDim.x)
        atomicAdd(&s[b[i]], 1);
    __syncthreads();
    for (int i = threadIdx.x; i < NGR; i += blockDim.x) if (s[i]) atomicAdd(&cnt[i], s[i]);
}

// ---- fused: C_tile = A_tile @ W; 128 threads, per-thread 8 rows x 8 cols (f32x2).
//      All 16 LDS.128 for a k4-chunk are hoisted to the chunk top so the 29-cycle
//      LDS latency is exposed once per chunk, then covered by 128 FFMA2.
//      If NORM: apply GraphNorm-1 affine to A rows and write them back as x_1_out.
//      Else:    pass A tile through to wb (x_2 output copy).
//      Then scatter-add DEG entries per source row into agg (v4 global red).
//      cols are structured: col(e) = e / DEG, so no cols array needed. ----
template<int DEG, bool NORM>
__global__ __launch_bounds__(128) void fused_gemm_scatter(
    const float* __restrict__ A, const float* __restrict__ W,
    const int* __restrict__ rows, const float* __restrict__ vals,
    float* __restrict__ agg,
    const int* __restrict__ batch, float* __restrict__ wb, int n)
{
    extern __shared__ float smem[];
    float* Ws = smem;                         // CN*CN floats (reused as C tile later)
    float* As = smem + CN*CN;                 // BT*AP floats
    int*   s_rows = (int*)(As + BT*AP);       // BT*DEG
    float* s_vals = (float*)(s_rows + BT*DEG);

    const int tid  = threadIdx.x;
    const int j0   = blockIdx.x * BT;
    const int nrow = min(BT, n - j0);

    // load W (row-major [k][c]) into smem
    {
        const float4* W4 = (const float4*)W;
        float4* Ws4 = (float4*)Ws;
        for (int i = tid; i < CN*CN/4; i += 128) Ws4[i] = W4[i];
    }
    // load A tile; NORM: normalize + write back as output; else pass-through copy
    {
        const float4* A4 = (const float4*)A;
        for (int i = tid; i < BT*32; i += 128) {
            int r = i >> 5, cq = i & 31;
            float4 v = make_float4(0.f, 0.f, 0.f, 0.f);
            if (r < nrow) {
                long idx = (long)(j0 + r) * 32 + cq;
                v = A4[idx];
                if (NORM) {
                    int g = batch[j0 + r];
                    float4 a = ((const float4*)g_scale1)[g*32 + cq];
                    float4 b = ((const float4*)g_shift1)[g*32 + cq];
                    v.x = v.x*a.x + b.x; v.y = v.y*a.y + b.y;
                    v.z = v.z*a.z + b.z; v.w = v.w*a.w + b.w;
                }
                ((float4*)wb)[idx] = v;
            }
            *(float4*)&As[r*AP + cq*4] = v;
        }
    }
    // stage scatter metadata (rows + vals; cols are implicit)
    for (int i = tid; i < nrow*DEG; i += 128) {
        long e = (long)j0*DEG + i;
        s_rows[i] = rows[e];
        s_vals[i] = vals[e];
    }
    __syncthreads();

    // GEMM: thread computes rows r0..r0+7, cols c0..c0+7 (4 f32x2 per row)
    const int c0 = (tid & 15) << 3;
    const int r0 = (tid >> 4) << 3;
    unsigned long long acc[32];
#pragma unroll
    for (int i = 0; i < 32; i++) acc[i] = 0ULL;

    const float* A0 = &As[r0*AP];
    union WU { float4 f; unsigned long long u[2]; };

#pragma unroll 2
    for (int k4 = 0; k4 < CN; k4 += 4) {
        // chunk-top load batch: 8 A float4 + 8 W float4 (one latency exposure)
        float4 av[8];
#pragma unroll
        for (int i = 0; i < 8; i++) av[i] = *(const float4*)&A0[i*AP + k4];
        WU w[8];
#pragma unroll
        for (int kk = 0; kk < 4; kk++) {
            w[2*kk+0].f = *(const float4*)&Ws[(k4+kk)*CN + c0];
            w[2*kk+1].f = *(const float4*)&Ws[(k4+kk)*CN + c0 + 4];
        }
#pragma unroll
        for (int kk = 0; kk < 4; kk++) {
#pragma unroll
            for (int i = 0; i < 8; i++) {
                float as = (kk == 0) ? av[i].x : (kk == 1) ? av[i].y : (kk == 2) ? av[i].z : av[i].w;
                unsigned long long a = pack2(as);
                fma2(acc[i*4+0], a, w[2*kk+0].u[0]);
                fma2(acc[i*4+1], a, w[2*kk+0].u[1]);
                fma2(acc[i*4+2], a, w[2*kk+1].u[0]);
                fma2(acc[i*4+3], a, w[2*kk+1].u[1]);
            }
        }
    }
    __syncthreads();   // all warps done reading W -> reuse region as C tile

    float* Cs = Ws;    // BT x CP
#pragma unroll
    for (int i = 0; i < 8; i++) {
        float2* dst = (float2*)&Cs[(r0+i)*CP + c0];
#pragma unroll
        for (int j = 0; j < 4; j++) {
            union { unsigned long long u; float2 f; } t;
            t.u = acc[i*4+j];
            dst[j] = t.f;
        }
    }
    __syncthreads();

    // scatter: one v4 reduction per (entry, 4-channel group); src col = e/DEG
    const int total = nrow * DEG * 32;
    for (int idx = tid; idx < total; idx += 128) {
        int e = idx >> 5, q = idx & 31;
        int src = e / DEG;
        float v = s_vals[e];
        float4 y = *(const float4*)&Cs[src*CP + q*4];
        float* p = agg + (long)s_rows[e]*CN + q*4;
        red4(p, v*y.x, v*y.y, v*y.z, v*y.w);
    }
}

// ---- per-(graph,channel) sum and sumsq with block-local segmented runs (batch sorted) ----
__global__ void stats_kernel(const float* __restrict__ y, const int* __restrict__ batch,
                             int n, int which)
{
    float* sum = which ? g_sum2 : g_sum1;
    float* sq  = which ? g_sq2  : g_sq1;
    int c  = threadIdx.x & (CN-1);
    int p  = threadIdx.x >> 7;
    int r0 = blockIdx.x * SROWS;
    int rend = min(r0 + SROWS, n);
    float rs = 0.f, rq = 0.f;
    int cur = -1;
    for (int r = r0 + p; r < rend; r += 2) {
        int g = batch[r];
        if (g != cur) {
            if (cur >= 0) { atomicAdd(&sum[cur*CN+c], rs); atomicAdd(&sq[cur*CN+c], rq); }
            cur = g; rs = 0.f; rq = 0.f;
        }
        float v = y[(long)r*CN + c];
        rs += v; rq += v*v;
    }
    if (cur >= 0) { atomicAdd(&sum[cur*CN+c], rs); atomicAdd(&sq[cur*CN+c], rq); }
}

// ---- turn sums into per-(graph,channel) affine scale/shift ----
__global__ void finalize_kernel(const float* __restrict__ wgt, const float* __restrict__ bias,
                                const float* __restrict__ mscale, int which)
{
    int i = blockIdx.x*blockDim.x + threadIdx.x;
    if (i >= NGR*CN) return;
    const float* sum = which ? g_sum2 : g_sum1;
    const float* sq  = which ? g_sq2  : g_sq1;
    const int*   cnt = which ? g_cnt2 : g_cnt1;
    float* sc = which ? g_scale2 : g_scale1;
    float* sh = which ? g_shift2 : g_shift1;
    int g = i >> 7, c = i & (CN-1);
    float nf  = fmaxf((float)cnt[g], 1.f);
    float m   = sum[i] / nf;
    float ms  = m * mscale[c];
    float var = sq[i]/nf - 2.f*ms*m + ms*ms;   // E[(x - m*s)^2]
    float inv = rsqrtf(var + EPSV);
    float a   = wgt[c] * inv;
    sc[i] = a;
    sh[i] = bias[c] - ms * a;
}

// ---- final normalization of x_0_out (GraphNorm-2 application) ----
__global__ void apply_norm_kernel(float* __restrict__ y, const int* __restrict__ batch, int n)
{
    long idx = (long)blockIdx.x*blockDim.x + threadIdx.x;   // one float4
    if (idx >= (long)n*32) return;
    int r = (int)(idx >> 5); int cq = (int)(idx & 31);
    int g = batch[r];
    float4 v = ((float4*)y)[idx];
    float4 a = ((const float4*)g_scale2)[g*32+cq];
    float4 b = ((const float4*)g_shift2)[g*32+cq];
    v.x = v.x*a.x + b.x; v.y = v.y*a.y + b.y;
    v.z = v.z*a.z + b.z; v.w = v.w*a.w + b.w;
    ((float4*)y)[idx] = v;
}

extern "C" void kernel_launch(void* const* d_in, const int* in_sizes, int n_in,
                              void* d_out, int out_size)
{
    const float* x0   = (const float*)d_in[0];
    const float* x1   = (const float*)d_in[1];
    const float* x2   = (const float*)d_in[2];
    const float* W1   = (const float*)d_in[3];
    const float* W2   = (const float*)d_in[4];
    const float* gn1w = (const float*)d_in[5];
    const float* gn1b = (const float*)d_in[6];
    const float* gn1m = (const float*)d_in[7];
    const float* gn2w = (const float*)d_in[8];
    const float* gn2b = (const float*)d_in[9];
    const float* gn2m = (const float*)d_in[10];
    const int*   i2r  = (const int*)d_in[11];
    // d_in[12] = inc2_cols (structured, unused)
    const float* i2v  = (const float*)d_in[13];
    const int*   i1r  = (const int*)d_in[14];
    // d_in[15] = inc1_cols (structured, unused)
    const float* i1v  = (const float*)d_in[16];
    const int*   bn   = (const int*)d_in[17];
    const int*   be   = (const int*)d_in[18];

    const int n0 = in_sizes[0] / CN;
    const int n1 = in_sizes[1] / CN;
    const int n2 = in_sizes[2] / CN;

    float* out_x0 = (float*)d_out;
    float* out_x1 = out_x0 + (size_t)n0 * CN;
    float* out_x2 = out_x1 + (size_t)n1 * CN;

    const size_t SM3 = (size_t)(CN*CN + BT*AP)*4 + (size_t)BT*3*8;
    const size_t SM2 = (size_t)(CN*CN + BT*AP)*4 + (size_t)BT*2*8;
    cudaFuncSetAttribute((const void*)fused_gemm_scatter<3,false>,
                         cudaFuncAttributeMaxDynamicSharedMemorySize, (int)SM3);
    cudaFuncSetAttribute((const void*)fused_gemm_scatter<2,true>,
                         cudaFuncAttributeMaxDynamicSharedMemorySize, (int)SM2);

    // residual pre-fill of outputs (x_2 copy is fused into GEMM1's A-load)
    cudaMemcpyAsync(out_x0, x0, (size_t)n0*CN*sizeof(float), cudaMemcpyDeviceToDevice, 0);
    cudaMemcpyAsync(out_x1, x1, (size_t)n1*CN*sizeof(float), cudaMemcpyDeviceToDevice, 0);

    zero_stats_kernel<<<64, 256>>>();
    count_kernel<<<232, 256>>>(be, n1, 0);
    count_kernel<<<232, 256>>>(bn, n0, 1);

    // layer 1: out_x1 += inc2 @ (x_2 @ W1); out_x2 = x_2 (fused copy)
    fused_gemm_scatter<3,false><<<(n2+BT-1)/BT, 128, SM3>>>(
        x2, W1, i2r, i2v, out_x1, nullptr, out_x2, n2);
    stats_kernel<<<(n1+SROWS-1)/SROWS, 256>>>(out_x1, be, n1, 0);
    finalize_kernel<<<64, 256>>>(gn1w, gn1b, gn1m, 0);

    // layer 2: normalize x_1_out in-flight, out_x0 += inc1 @ (x_1_out @ W2)
    fused_gemm_scatter<2,true><<<(n1+BT-1)/BT, 128, SM2>>>(
        out_x1, W2, i1r, i1v, out_x0, be, out_x1, n1);
    stats_kernel<<<(n0+SROWS-1)/SROWS, 256>>>(out_x0, bn, n0, 1);
    finalize_kernel<<<64, 256>>>(gn2w, gn2b, gn2m, 1);
    apply_norm_kernel<<<(int)(((long)n0*32 + 255)/256), 256>>>(out_x0, bn, n0);
}

// round 11
// speedup vs baseline: 1.3229x; 1.1293x over previous
#include <cuda_runtime.h>
#include <stdint.h>

#define CN 128      // channels
#define NGR 128     // num graphs
#define BT 64       // rows per GEMM block tile
#define AP 132      // padded smem pitch (floats) for A/C tile (>= CN, float4-aligned)
#define CP 132      // pitch for C tile (aliases A)
#define SROWS 512   // rows per stats block
#define EPSV 1e-5f

// ---- small device-global scratch (statistics only; big buffers live in d_out) ----
__device__ float g_sum1[NGR*CN];
__device__ float g_sq1 [NGR*CN];
__device__ float g_sum2[NGR*CN];
__device__ float g_sq2 [NGR*CN];
__device__ float g_scale1[NGR*CN];
__device__ float g_shift1[NGR*CN];
__device__ float g_scale2[NGR*CN];
__device__ float g_shift2[NGR*CN];
__device__ int   g_cnt1[NGR];
__device__ int   g_cnt2[NGR];

// ---- Blackwell packed-fp32 helpers ----
__device__ __forceinline__ unsigned long long pack2(float a) {
    unsigned int u = __float_as_uint(a);
    unsigned long long r;
    asm("mov.b64 %0, {%1, %1};" : "=l"(r) : "r"(u));
    return r;
}
__device__ __forceinline__ void fma2(unsigned long long& d, unsigned long long a, unsigned long long b) {
    asm("fma.rn.f32x2 %0, %1, %2, %0;" : "+l"(d) : "l"(a), "l"(b));
}
__device__ __forceinline__ void red4(float* p, float x, float y, float z, float w) {
    asm volatile("red.global.add.v4.f32 [%0], {%1,%2,%3,%4};"
                 :: "l"(p), "f"(x), "f"(y), "f"(z), "f"(w) : "memory");
}

// ---- zero the small stats buffers ----
__global__ void zero_stats_kernel() {
    int i = blockIdx.x * blockDim.x + threadIdx.x;
    if (i < NGR*CN) { g_sum1[i]=0.f; g_sq1[i]=0.f; g_sum2[i]=0.f; g_sq2[i]=0.f; }
    if (i < NGR)    { g_cnt1[i]=0;   g_cnt2[i]=0; }
}

// ---- per-graph element counts (batch histogram) ----
__global__ void count_kernel(const int* __restrict__ b, int n, int which) {
    __shared__ int s[NGR];
    int* cnt = which ? g_cnt2 : g_cnt1;
    for (int i = threadIdx.x; i < NGR; i += blockDim.x) s[i] = 0;
    __syncthreads();
    for (long i = (long)blockIdx.x*blockDim.x + threadIdx.x; i < n; i += (long)gridDim.x*blockDim.x)
        atomicAdd(&s[b[i]], 1);
    __syncthreads();
    for (int i = threadIdx.x; i < NGR; i += blockDim.x) if (s[i]) atomicAdd(&cnt[i], s[i]);
}

// ---- fused: C_tile = A_tile @ W; 128 threads, per-thread 8 rows x 8 cols (f32x2).
//      W is NOT staged in smem: it is read via LDG.128 and stays L1-resident
//      (A uses streaming hints), freeing smem so 4 blocks/SM fit (4 warps/SMSP).
//      C tile aliases the A tile (A fully consumed before C written).
//      If NORM: apply GraphNorm-1 affine to A rows and write them back as x_1_out.
//      Else:    pass A tile through to wb (x_2 output copy).
//      Then scatter-add DEG entries per source row into agg (v4 global red).
//      cols are structured: col(e) = e / DEG, so no cols array needed. ----
template<int DEG, bool NORM>
__global__ __launch_bounds__(128, 4) void fused_gemm_scatter(
    const float* __restrict__ A, const float* __restrict__ W,
    const int* __restrict__ rows, const float* __restrict__ vals,
    float* __restrict__ agg,
    const int* __restrict__ batch, float* __restrict__ wb, int n)
{
    extern __shared__ float smem[];
    float* As = smem;                         // BT*AP floats (reused as C tile later)
    int*   s_rows = (int*)(As + BT*AP);       // BT*DEG
    float* s_vals = (float*)(s_rows + BT*DEG);

    const int tid  = threadIdx.x;
    const int j0   = blockIdx.x * BT;
    const int nrow = min(BT, n - j0);

    // load A tile; NORM: normalize + write back as output; else pass-through copy
    {
        const float4* A4 = (const float4*)A;
        for (int i = tid; i < BT*32; i += 128) {
            int r = i >> 5, cq = i & 31;
            float4 v = make_float4(0.f, 0.f, 0.f, 0.f);
            if (r < nrow) {
                long idx = (long)(j0 + r) * 32 + cq;
                v = __ldcs(&A4[idx]);                 // streaming: keep W in L1
                if (NORM) {
                    int g = batch[j0 + r];
                    float4 a = ((const float4*)g_scale1)[g*32 + cq];
                    float4 b = ((const float4*)g_shift1)[g*32 + cq];
                    v.x = v.x*a.x + b.x; v.y = v.y*a.y + b.y;
                    v.z = v.z*a.z + b.z; v.w = v.w*a.w + b.w;
                }
                __stcs(&((float4*)wb)[idx], v);       // streaming write
            }
            *(float4*)&As[r*AP + cq*4] = v;
        }
    }
    // stage scatter metadata (rows + vals; cols are implicit)
    for (int i = tid; i < nrow*DEG; i += 128) {
        long e = (long)j0*DEG + i;
        s_rows[i] = rows[e];
        s_vals[i] = vals[e];
    }
    __syncthreads();

    // GEMM: thread computes rows r0..r0+7, cols c0..c0+7 (4 f32x2 per row)
    const int c0 = (tid & 15) << 3;
    const int r0 = (tid >> 4) << 3;
    unsigned long long acc[32];
#pragma unroll
    for (int i = 0; i < 32; i++) acc[i] = 0ULL;

    const float* A0 = &As[r0*AP];
    union WU { float4 f; unsigned long long u[2]; };

#pragma unroll 1
    for (int k4 = 0; k4 < CN; k4 += 4) {
        // A slice for this 4-k chunk: 8 LDS.128 (2-address broadcast, 1 wf each)
        float4 av[8];
#pragma unroll
        for (int i = 0; i < 8; i++) av[i] = *(const float4*)&A0[i*AP + k4];

        // W rows k4+0, k4+1 via L1-resident LDG.128
        WU w[4];
        w[0].f = __ldg((const float4*)&W[(k4+0)*CN + c0]);
        w[1].f = __ldg((const float4*)&W[(k4+0)*CN + c0 + 4]);
        w[2].f = __ldg((const float4*)&W[(k4+1)*CN + c0]);
        w[3].f = __ldg((const float4*)&W[(k4+1)*CN + c0 + 4]);
#pragma unroll
        for (int i = 0; i < 8; i++) {
            unsigned long long a = pack2(av[i].x);
            fma2(acc[i*4+0], a, w[0].u[0]);
            fma2(acc[i*4+1], a, w[0].u[1]);
            fma2(acc[i*4+2], a, w[1].u[0]);
            fma2(acc[i*4+3], a, w[1].u[1]);
        }
#pragma unroll
        for (int i = 0; i < 8; i++) {
            unsigned long long a = pack2(av[i].y);
            fma2(acc[i*4+0], a, w[2].u[0]);
            fma2(acc[i*4+1], a, w[2].u[1]);
            fma2(acc[i*4+2], a, w[3].u[0]);
            fma2(acc[i*4+3], a, w[3].u[1]);
        }

        // W rows k4+2, k4+3
        w[0].f = __ldg((const float4*)&W[(k4+2)*CN + c0]);
        w[1].f = __ldg((const float4*)&W[(k4+2)*CN + c0 + 4]);
        w[2].f = __ldg((const float4*)&W[(k4+3)*CN + c0]);
        w[3].f = __ldg((const float4*)&W[(k4+3)*CN + c0 + 4]);
#pragma unroll
        for (int i = 0; i < 8; i++) {
            unsigned long long a = pack2(av[i].z);
            fma2(acc[i*4+0], a, w[0].u[0]);
            fma2(acc[i*4+1], a, w[0].u[1]);
            fma2(acc[i*4+2], a, w[1].u[0]);
            fma2(acc[i*4+3], a, w[1].u[1]);
        }
#pragma unroll
        for (int i = 0; i < 8; i++) {
            unsigned long long a = pack2(av[i].w);
            fma2(acc[i*4+0], a, w[2].u[0]);
            fma2(acc[i*4+1], a, w[2].u[1]);
            fma2(acc[i*4+2], a, w[3].u[0]);
            fma2(acc[i*4+3], a, w[3].u[1]);
        }
    }
    __syncthreads();   // A fully consumed -> C tile may overwrite it

    float* Cs = As;    // BT x CP (aliases A tile)
#pragma unroll
    for (int i = 0; i < 8; i++) {
        float2* dst = (float2*)&Cs[(r0+i)*CP + c0];
#pragma unroll
        for (int j = 0; j < 4; j++) {
            union { unsigned long long u; float2 f; } t;
            t.u = acc[i*4+j];
            dst[j] = t.f;
        }
    }
    __syncthreads();

    // scatter: one v4 reduction per (entry, 4-channel group); src col = e/DEG
    const int total = nrow * DEG * 32;
    for (int idx = tid; idx < total; idx += 128) {
        int e = idx >> 5, q = idx & 31;
        int src = e / DEG;
        float v = s_vals[e];
        float4 y = *(const float4*)&Cs[src*CP + q*4];
        float* p = agg + (long)s_rows[e]*CN + q*4;
        red4(p, v*y.x, v*y.y, v*y.z, v*y.w);
    }
}

// ---- per-(graph,channel) sum and sumsq with block-local segmented runs (batch sorted) ----
__global__ void stats_kernel(const float* __restrict__ y, const int* __restrict__ batch,
                             int n, int which)
{
    float* sum = which ? g_sum2 : g_sum1;
    float* sq  = which ? g_sq2  : g_sq1;
    int c  = threadIdx.x & (CN-1);
    int p  = threadIdx.x >> 7;
    int r0 = blockIdx.x * SROWS;
    int rend = min(r0 + SROWS, n);
    float rs = 0.f, rq = 0.f;
    int cur = -1;
    for (int r = r0 + p; r < rend; r += 2) {
        int g = batch[r];
        if (g != cur) {
            if (cur >= 0) { atomicAdd(&sum[cur*CN+c], rs); atomicAdd(&sq[cur*CN+c], rq); }
            cur = g; rs = 0.f; rq = 0.f;
        }
        float v = y[(long)r*CN + c];
        rs += v; rq += v*v;
    }
    if (cur >= 0) { atomicAdd(&sum[cur*CN+c], rs); atomicAdd(&sq[cur*CN+c], rq); }
}

// ---- turn sums into per-(graph,channel) affine scale/shift ----
__global__ void finalize_kernel(const float* __restrict__ wgt, const float* __restrict__ bias,
                                const float* __restrict__ mscale, int which)
{
    int i = blockIdx.x*blockDim.x + threadIdx.x;
    if (i >= NGR*CN) return;
    const float* sum = which ? g_sum2 : g_sum1;
    const float* sq  = which ? g_sq2  : g_sq1;
    const int*   cnt = which ? g_cnt2 : g_cnt1;
    float* sc = which ? g_scale2 : g_scale1;
    float* sh = which ? g_shift2 : g_shift1;
    int g = i >> 7, c = i & (CN-1);
    float nf  = fmaxf((float)cnt[g], 1.f);
    float m   = sum[i] / nf;
    float ms  = m * mscale[c];
    float var = sq[i]/nf - 2.f*ms*m + ms*ms;   // E[(x - m*s)^2]
    float inv = rsqrtf(var + EPSV);
    float a   = wgt[c] * inv;
    sc[i] = a;
    sh[i] = bias[c] - ms * a;
}

// ---- final normalization of x_0_out (GraphNorm-2 application) ----
__global__ void apply_norm_kernel(float* __restrict__ y, const int* __restrict__ batch, int n)
{
    long idx = (long)blockIdx.x*blockDim.x + threadIdx.x;   // one float4
    if (idx >= (long)n*32) return;
    int r = (int)(idx >> 5); int cq = (int)(idx & 31);
    int g = batch[r];
    float4 v = ((float4*)y)[idx];
    float4 a = ((const float4*)g_scale2)[g*32+cq];
    float4 b = ((const float4*)g_shift2)[g*32+cq];
    v.x = v.x*a.x + b.x; v.y = v.y*a.y + b.y;
    v.z = v.z*a.z + b.z; v.w = v.w*a.w + b.w;
    ((float4*)y)[idx] = v;
}

extern "C" void kernel_launch(void* const* d_in, const int* in_sizes, int n_in,
                              void* d_out, int out_size)
{
    const float* x0   = (const float*)d_in[0];
    const float* x1   = (const float*)d_in[1];
    const float* x2   = (const float*)d_in[2];
    const float* W1   = (const float*)d_in[3];
    const float* W2   = (const float*)d_in[4];
    const float* gn1w = (const float*)d_in[5];
    const float* gn1b = (const float*)d_in[6];
    const float* gn1m = (const float*)d_in[7];
    const float* gn2w = (const float*)d_in[8];
    const float* gn2b = (const float*)d_in[9];
    const float* gn2m = (const float*)d_in[10];
    const int*   i2r  = (const int*)d_in[11];
    // d_in[12] = inc2_cols (structured, unused)
    const float* i2v  = (const float*)d_in[13];
    const int*   i1r  = (const int*)d_in[14];
    // d_in[15] = inc1_cols (structured, unused)
    const float* i1v  = (const float*)d_in[16];
    const int*   bn   = (const int*)d_in[17];
    const int*   be   = (const int*)d_in[18];

    const int n0 = in_sizes[0] / CN;
    const int n1 = in_sizes[1] / CN;
    const int n2 = in_sizes[2] / CN;

    float* out_x0 = (float*)d_out;
    float* out_x1 = out_x0 + (size_t)n0 * CN;
    float* out_x2 = out_x1 + (size_t)n1 * CN;

    const size_t SM3 = (size_t)(BT*AP)*4 + (size_t)BT*3*8;
    const size_t SM2 = (size_t)(BT*AP)*4 + (size_t)BT*2*8;

    // residual pre-fill of outputs (x_2 copy is fused into GEMM1's A-load)
    cudaMemcpyAsync(out_x0, x0, (size_t)n0*CN*sizeof(float), cudaMemcpyDeviceToDevice, 0);
    cudaMemcpyAsync(out_x1, x1, (size_t)n1*CN*sizeof(float), cudaMemcpyDeviceToDevice, 0);

    zero_stats_kernel<<<64, 256>>>();
    count_kernel<<<232, 256>>>(be, n1, 0);
    count_kernel<<<232, 256>>>(bn, n0, 1);

    // layer 1: out_x1 += inc2 @ (x_2 @ W1); out_x2 = x_2 (fused copy)
    fused_gemm_scatter<3,false><<<(n2+BT-1)/BT, 128, SM3>>>(
        x2, W1, i2r, i2v, out_x1, nullptr, out_x2, n2);
    stats_kernel<<<(n1+SROWS-1)/SROWS, 256>>>(out_x1, be, n1, 0);
    finalize_kernel<<<64, 256>>>(gn1w, gn1b, gn1m, 0);

    // layer 2: normalize x_1_out in-flight, out_x0 += inc1 @ (x_1_out @ W2)
    fused_gemm_scatter<2,true><<<(n1+BT-1)/BT, 128, SM2>>>(
        out_x1, W2, i1r, i1v, out_x0, be, out_x1, n1);
    stats_kernel<<<(n0+SROWS-1)/SROWS, 256>>>(out_x0, bn, n0, 1);
    finalize_kernel<<<64, 256>>>(gn2w, gn2b, gn2m, 1);
    apply_norm_kernel<<<(int)(((long)n0*32 + 255)/256), 256>>>(out_x0, bn, n0);
}

// round 12
// speedup vs baseline: 1.4670x; 1.1089x over previous
#include <cuda_runtime.h>
#include <stdint.h>

#define CN 128      // channels
#define NGR 128     // num graphs
#define BT 64       // rows per GEMM block tile
#define AP 132      // padded smem pitch (floats) for A/C tile (>= CN, float4-aligned)
#define CP 132      // pitch for C tile (aliases A)
#define SROWS 512   // rows per stats block
#define EPSV 1e-5f

// ---- small device-global scratch (statistics only; big buffers live in d_out) ----
__device__ float g_sum1[NGR*CN];
__device__ float g_sq1 [NGR*CN];
__device__ float g_sum2[NGR*CN];
__device__ float g_sq2 [NGR*CN];
__device__ float g_scale1[NGR*CN];
__device__ float g_shift1[NGR*CN];
__device__ float g_scale2[NGR*CN];
__device__ float g_shift2[NGR*CN];
__device__ int   g_cnt1[NGR];
__device__ int   g_cnt2[NGR];

// ---- Blackwell packed-fp32 helpers ----
__device__ __forceinline__ unsigned long long pack2(float a) {
    unsigned int u = __float_as_uint(a);
    unsigned long long r;
    asm("mov.b64 %0, {%1, %1};" : "=l"(r) : "r"(u));
    return r;
}
__device__ __forceinline__ void fma2(unsigned long long& d, unsigned long long a, unsigned long long b) {
    asm("fma.rn.f32x2 %0, %1, %2, %0;" : "+l"(d) : "l"(a), "l"(b));
}
__device__ __forceinline__ void red4(float* p, float x, float y, float z, float w) {
    asm volatile("red.global.add.v4.f32 [%0], {%1,%2,%3,%4};"
                 :: "l"(p), "f"(x), "f"(y), "f"(z), "f"(w) : "memory");
}

// ---- zero the small stats buffers ----
__global__ void zero_stats_kernel() {
    int i = blockIdx.x * blockDim.x + threadIdx.x;
    if (i < NGR*CN) { g_sum1[i]=0.f; g_sq1[i]=0.f; g_sum2[i]=0.f; g_sq2[i]=0.f; }
    if (i < NGR)    { g_cnt1[i]=0;   g_cnt2[i]=0; }
}

// ---- per-graph element counts (batch histogram) ----
__global__ void count_kernel(const int* __restrict__ b, int n, int which) {
    __shared__ int s[NGR];
    int* cnt = which ? g_cnt2 : g_cnt1;
    for (int i = threadIdx.x; i < NGR; i += blockDim.x) s[i] = 0;
    __syncthreads();
    for (long i = (long)blockIdx.x*blockDim.x + threadIdx.x; i < n; i += (long)gridDim.x*blockDim.x)
        atomicAdd(&s[b[i]], 1);
    __syncthreads();
    for (int i = threadIdx.x; i < NGR; i += blockDim.x) if (s[i]) atomicAdd(&cnt[i], s[i]);
}

// ---- fused: C_tile = A_tile @ W; 128 threads, per-thread 8 rows x 8 cols (f32x2).
//      W is read via LDG.128 (L1-resident) with REGISTER DOUBLE-BUFFERING:
//      W rows for k-step n+1 are prefetched while step n's FFMA2s execute,
//      so the LDG latency never sits on the critical path.
//      C tile aliases the A tile. smem ~35KB -> 4 blocks/SM (16 warps).
//      If NORM: apply GraphNorm-1 affine to A rows and write them back as x_1_out.
//      Else:    pass A tile through to wb_out (x_2 output copy).
//      Then scatter-add DEG entries per source row into agg (v4 global red). ----
template<int DEG, bool NORM>
__global__ __launch_bounds__(128, 4) void fused_gemm_scatter(
    const float* __restrict__ A, const float* __restrict__ W,
    const int* __restrict__ rows, const float* __restrict__ vals,
    float* __restrict__ agg,
    const int* __restrict__ batch, float* __restrict__ wb_out, int n)
{
    extern __shared__ float smem[];
    float* As = smem;                         // BT*AP floats (reused as C tile later)
    int*   s_rows = (int*)(As + BT*AP);       // BT*DEG
    float* s_vals = (float*)(s_rows + BT*DEG);

    const int tid  = threadIdx.x;
    const int j0   = blockIdx.x * BT;
    const int nrow = min(BT, n - j0);

    // load A tile; NORM: normalize + write back as output; else pass-through copy
    {
        const float4* A4 = (const float4*)A;
        for (int i = tid; i < BT*32; i += 128) {
            int r = i >> 5, cq = i & 31;
            float4 v = make_float4(0.f, 0.f, 0.f, 0.f);
            if (r < nrow) {
                long idx = (long)(j0 + r) * 32 + cq;
                v = __ldcs(&A4[idx]);                 // streaming: keep W in L1
                if (NORM) {
                    int g = batch[j0 + r];
                    float4 a = ((const float4*)g_scale1)[g*32 + cq];
                    float4 b = ((const float4*)g_shift1)[g*32 + cq];
                    v.x = v.x*a.x + b.x; v.y = v.y*a.y + b.y;
                    v.z = v.z*a.z + b.z; v.w = v.w*a.w + b.w;
                }
                __stcs(&((float4*)wb_out)[idx], v);   // streaming write
            }
            *(float4*)&As[r*AP + cq*4] = v;
        }
    }
    // stage scatter metadata (rows + vals; cols are implicit)
    for (int i = tid; i < nrow*DEG; i += 128) {
        long e = (long)j0*DEG + i;
        s_rows[i] = rows[e];
        s_vals[i] = vals[e];
    }
    __syncthreads();

    // GEMM: thread computes rows r0..r0+7, cols c0..c0+7 (4 f32x2 per row)
    const int c0 = (tid & 15) << 3;
    const int r0 = (tid >> 4) << 3;
    unsigned long long acc[32];
#pragma unroll
    for (int i = 0; i < 32; i++) acc[i] = 0ULL;

    const float* A0 = &As[r0*AP];
    union WU { float4 f; unsigned long long u[2]; };

    // prime pipeline: W rows 0,1 in wa
    WU wa[4], wb[4];
    wa[0].f = __ldg((const float4*)&W[0*CN + c0]);
    wa[1].f = __ldg((const float4*)&W[0*CN + c0 + 4]);
    wa[2].f = __ldg((const float4*)&W[1*CN + c0]);
    wa[3].f = __ldg((const float4*)&W[1*CN + c0 + 4]);

#pragma unroll 1
    for (int k4 = 0; k4 < CN; k4 += 4) {
        // prefetch W rows k4+2, k4+3 into wb (covered by phase-1 FMAs)
        wb[0].f = __ldg((const float4*)&W[(k4+2)*CN + c0]);
        wb[1].f = __ldg((const float4*)&W[(k4+2)*CN + c0 + 4]);
        wb[2].f = __ldg((const float4*)&W[(k4+3)*CN + c0]);
        wb[3].f = __ldg((const float4*)&W[(k4+3)*CN + c0 + 4]);

        // phase 1: k rows k4, k4+1 with wa (A reloaded per 4-row half, regs stay low)
#pragma unroll
        for (int h = 0; h < 2; h++) {
            float4 av[4];
#pragma unroll
            for (int i = 0; i < 4; i++) av[i] = *(const float4*)&A0[(h*4+i)*AP + k4];
#pragma unroll
            for (int i = 0; i < 4; i++) {
                const int ai = h*4 + i;
                unsigned long long a = pack2(av[i].x);
                fma2(acc[ai*4+0], a, wa[0].u[0]);
                fma2(acc[ai*4+1], a, wa[0].u[1]);
                fma2(acc[ai*4+2], a, wa[1].u[0]);
                fma2(acc[ai*4+3], a, wa[1].u[1]);
                a = pack2(av[i].y);
                fma2(acc[ai*4+0], a, wa[2].u[0]);
                fma2(acc[ai*4+1], a, wa[2].u[1]);
                fma2(acc[ai*4+2], a, wa[3].u[0]);
                fma2(acc[ai*4+3], a, wa[3].u[1]);
            }
        }

        // prefetch W rows k4+4, k4+5 into wa (wraps harmlessly on last iter)
        {
            const int kn = (k4 + 4) & (CN - 1);
            wa[0].f = __ldg((const float4*)&W[kn*CN + c0]);
            wa[1].f = __ldg((const float4*)&W[kn*CN + c0 + 4]);
            wa[2].f = __ldg((const float4*)&W[(kn+1)*CN + c0]);
            wa[3].f = __ldg((const float4*)&W[(kn+1)*CN + c0 + 4]);
        }

        // phase 2: k rows k4+2, k4+3 with wb
#pragma unroll
        for (int h = 0; h < 2; h++) {
            float4 av[4];
#pragma unroll
            for (int i = 0; i < 4; i++) av[i] = *(const float4*)&A0[(h*4+i)*AP + k4];
#pragma unroll
            for (int i = 0; i < 4; i++) {
                const int ai = h*4 + i;
                unsigned long long a = pack2(av[i].z);
                fma2(acc[ai*4+0], a, wb[0].u[0]);
                fma2(acc[ai*4+1], a, wb[0].u[1]);
                fma2(acc[ai*4+2], a, wb[1].u[0]);
                fma2(acc[ai*4+3], a, wb[1].u[1]);
                a = pack2(av[i].w);
                fma2(acc[ai*4+0], a, wb[2].u[0]);
                fma2(acc[ai*4+1], a, wb[2].u[1]);
                fma2(acc[ai*4+2], a, wb[3].u[0]);
                fma2(acc[ai*4+3], a, wb[3].u[1]);
            }
        }
    }
    __syncthreads();   // A fully consumed -> C tile may overwrite it

    float* Cs = As;    // BT x CP (aliases A tile)
#pragma unroll
    for (int i = 0; i < 8; i++) {
        float2* dst = (float2*)&Cs[(r0+i)*CP + c0];
#pragma unroll
        for (int j = 0; j < 4; j++) {
            union { unsigned long long u; float2 f; } t;
            t.u = acc[i*4+j];
            dst[j] = t.f;
        }
    }
    __syncthreads();

    // scatter: one v4 reduction per (entry, 4-channel group); src col = e/DEG
    const int total = nrow * DEG * 32;
    for (int idx = tid; idx < total; idx += 128) {
        int e = idx >> 5, q = idx & 31;
        int src = e / DEG;
        float v = s_vals[e];
        float4 y = *(const float4*)&Cs[src*CP + q*4];
        float* p = agg + (long)s_rows[e]*CN + q*4;
        red4(p, v*y.x, v*y.y, v*y.z, v*y.w);
    }
}

// ---- per-(graph,channel) sum and sumsq with block-local segmented runs (batch sorted) ----
__global__ void stats_kernel(const float* __restrict__ y, const int* __restrict__ batch,
                             int n, int which)
{
    float* sum = which ? g_sum2 : g_sum1;
    float* sq  = which ? g_sq2  : g_sq1;
    int c  = threadIdx.x & (CN-1);
    int p  = threadIdx.x >> 7;
    int r0 = blockIdx.x * SROWS;
    int rend = min(r0 + SROWS, n);
    float rs = 0.f, rq = 0.f;
    int cur = -1;
    for (int r = r0 + p; r < rend; r += 2) {
        int g = batch[r];
        if (g != cur) {
            if (cur >= 0) { atomicAdd(&sum[cur*CN+c], rs); atomicAdd(&sq[cur*CN+c], rq); }
            cur = g; rs = 0.f; rq = 0.f;
        }
        float v = y[(long)r*CN + c];
        rs += v; rq += v*v;
    }
    if (cur >= 0) { atomicAdd(&sum[cur*CN+c], rs); atomicAdd(&sq[cur*CN+c], rq); }
}

// ---- turn sums into per-(graph,channel) affine scale/shift ----
__global__ void finalize_kernel(const float* __restrict__ wgt, const float* __restrict__ bias,
                                const float* __restrict__ mscale, int which)
{
    int i = blockIdx.x*blockDim.x + threadIdx.x;
    if (i >= NGR*CN) return;
    const float* sum = which ? g_sum2 : g_sum1;
    const float* sq  = which ? g_sq2  : g_sq1;
    const int*   cnt = which ? g_cnt2 : g_cnt1;
    float* sc = which ? g_scale2 : g_scale1;
    float* sh = which ? g_shift2 : g_shift1;
    int g = i >> 7, c = i & (CN-1);
    float nf  = fmaxf((float)cnt[g], 1.f);
    float m   = sum[i] / nf;
    float ms  = m * mscale[c];
    float var = sq[i]/nf - 2.f*ms*m + ms*ms;   // E[(x - m*s)^2]
    float inv = rsqrtf(var + EPSV);
    float a   = wgt[c] * inv;
    sc[i] = a;
    sh[i] = bias[c] - ms * a;
}

// ---- final normalization of x_0_out (GraphNorm-2 application) ----
__global__ void apply_norm_kernel(float* __restrict__ y, const int* __restrict__ batch, int n)
{
    long idx = (long)blockIdx.x*blockDim.x + threadIdx.x;   // one float4
    if (idx >= (long)n*32) return;
    int r = (int)(idx >> 5); int cq = (int)(idx & 31);
    int g = batch[r];
    float4 v = ((float4*)y)[idx];
    float4 a = ((const float4*)g_scale2)[g*32+cq];
    float4 b = ((const float4*)g_shift2)[g*32+cq];
    v.x = v.x*a.x + b.x; v.y = v.y*a.y + b.y;
    v.z = v.z*a.z + b.z; v.w = v.w*a.w + b.w;
    ((float4*)y)[idx] = v;
}

extern "C" void kernel_launch(void* const* d_in, const int* in_sizes, int n_in,
                              void* d_out, int out_size)
{
    const float* x0   = (const float*)d_in[0];
    const float* x1   = (const float*)d_in[1];
    const float* x2   = (const float*)d_in[2];
    const float* W1   = (const float*)d_in[3];
    const float* W2   = (const float*)d_in[4];
    const float* gn1w = (const float*)d_in[5];
    const float* gn1b = (const float*)d_in[6];
    const float* gn1m = (const float*)d_in[7];
    const float* gn2w = (const float*)d_in[8];
    const float* gn2b = (const float*)d_in[9];
    const float* gn2m = (const float*)d_in[10];
    const int*   i2r  = (const int*)d_in[11];
    // d_in[12] = inc2_cols (structured, unused)
    const float* i2v  = (const float*)d_in[13];
    const int*   i1r  = (const int*)d_in[14];
    // d_in[15] = inc1_cols (structured, unused)
    const float* i1v  = (const float*)d_in[16];
    const int*   bn   = (const int*)d_in[17];
    const int*   be   = (const int*)d_in[18];

    const int n0 = in_sizes[0] / CN;
    const int n1 = in_sizes[1] / CN;
    const int n2 = in_sizes[2] / CN;

    float* out_x0 = (float*)d_out;
    float* out_x1 = out_x0 + (size_t)n0 * CN;
    float* out_x2 = out_x1 + (size_t)n1 * CN;

    const size_t SM3 = (size_t)(BT*AP)*4 + (size_t)BT*3*8;
    const size_t SM2 = (size_t)(BT*AP)*4 + (size_t)BT*2*8;

    // residual pre-fill of outputs (x_2 copy is fused into GEMM1's A-load)
    cudaMemcpyAsync(out_x0, x0, (size_t)n0*CN*sizeof(float), cudaMemcpyDeviceToDevice, 0);
    cudaMemcpyAsync(out_x1, x1, (size_t)n1*CN*sizeof(float), cudaMemcpyDeviceToDevice, 0);

    zero_stats_kernel<<<64, 256>>>();
    count_kernel<<<232, 256>>>(be, n1, 0);
    count_kernel<<<232, 256>>>(bn, n0, 1);

    // layer 1: out_x1 += inc2 @ (x_2 @ W1); out_x2 = x_2 (fused copy)
    fused_gemm_scatter<3,false><<<(n2+BT-1)/BT, 128, SM3>>>(
        x2, W1, i2r, i2v, out_x1, nullptr, out_x2, n2);
    stats_kernel<<<(n1+SROWS-1)/SROWS, 256>>>(out_x1, be, n1, 0);
    finalize_kernel<<<64, 256>>>(gn1w, gn1b, gn1m, 0);

    // layer 2: normalize x_1_out in-flight, out_x0 += inc1 @ (x_1_out @ W2)
    fused_gemm_scatter<2,true><<<(n1+BT-1)/BT, 128, SM2>>>(
        out_x1, W2, i1r, i1v, out_x0, be, out_x1, n1);
    stats_kernel<<<(n0+SROWS-1)/SROWS, 256>>>(out_x0, bn, n0, 1);
    finalize_kernel<<<64, 256>>>(gn2w, gn2b, gn2m, 1);
    apply_norm_kernel<<<(int)(((long)n0*32 + 255)/256), 256>>>(out_x0, bn, n0);
}